// round 14
// baseline (speedup 1.0000x reference)
#include <cuda_runtime.h>
#include <cuda_fp16.h>
#include <math.h>
#include <stdint.h>

#define BB 256
#define TT 8
#define HH 1024
#define VV 32000
#define G4 4096

#define BK 64              // k elems per chunk (64 fp16 = 128 B row)
#define THREADS 256        // 8 warps: wm = wid&1 (m64), wn = wid>>1 (n32)

// CTA tile 128x128. Stage: [A 16K][B 16K]
#define OFF_B  16384
#define STAGE  32768
#define SMEM_GEMM (2 * STAGE)   // 65536 per CTA; 2 CTAs/SM
#define SWZ(off) ((off) ^ (((off) >> 3) & 0x70))

// ---------------------------------------------------------------------------
// scratch (device globals only)
// ---------------------------------------------------------------------------
__device__ __half g_hh[TT][BB][HH];    // h in fp16 (A operand)
__device__ float g_c[BB][HH];
__device__ float g_acc[4][BB][G4];     // split-K(4) partials for recurrent GEMM

// ---------------------------------------------------------------------------
// PTX helpers (sm_80-level only)
// ---------------------------------------------------------------------------
__device__ __forceinline__ uint32_t smem_to_u32(const void* p) {
    uint32_t a;
    asm("{ .reg .u64 t; cvta.to.shared.u64 t, %1; cvt.u32.u64 %0, t; }" : "=r"(a) : "l"(p));
    return a;
}
__device__ __forceinline__ void ldsm4(uint32_t* r, uint32_t addr) {
    asm volatile("ldmatrix.sync.aligned.m8n8.x4.shared.b16 {%0,%1,%2,%3}, [%4];"
                 : "=r"(r[0]), "=r"(r[1]), "=r"(r[2]), "=r"(r[3]) : "r"(addr));
}
__device__ __forceinline__ void mma16816(float* c, const uint32_t* a, const uint32_t* b) {
    asm volatile(
        "mma.sync.aligned.m16n8k16.row.col.f32.f16.f16.f32 "
        "{%0,%1,%2,%3}, {%4,%5,%6,%7}, {%8,%9}, {%0,%1,%2,%3};"
        : "+f"(c[0]), "+f"(c[1]), "+f"(c[2]), "+f"(c[3])
        : "r"(a[0]), "r"(a[1]), "r"(a[2]), "r"(a[3]), "r"(b[0]), "r"(b[1]));
}
__device__ __forceinline__ void cp16(uint32_t dst, const void* src) {
    asm volatile("cp.async.cg.shared.global [%0], [%1], 16;" :: "r"(dst), "l"(src));
}
#define CP_COMMIT() asm volatile("cp.async.commit_group;" ::: "memory")
#define CP_WAIT0()  asm volatile("cp.async.wait_group 0;" ::: "memory")

// ---------------------------------------------------------------------------
// Loaders (256 threads, CTA 128x128)
// ---------------------------------------------------------------------------
__device__ __forceinline__ void cpasync_A(const __half* __restrict__ Ag,
                                          uint32_t stage_u32, int kc, int tid) {
    #pragma unroll
    for (int u = 0; u < 4; u++) {
        const int idx = tid + u * THREADS;   // 0..1023
        const int row = idx >> 3;            // 0..127
        const int j   = idx & 7;
        const uint32_t off = SWZ((uint32_t)(row * 128 + j * 16));
        cp16(stage_u32 + off, Ag + (size_t)row * HH + kc * BK + j * 8);
    }
}

__device__ __forceinline__ void ldg_B(const float* __restrict__ Bg, int kc, int tid,
                                      float4* Bf) {
    #pragma unroll
    for (int it = 0; it < 8; it++) {
        const int idx = tid + it * THREADS;  // 0..2047
        const int row = idx >> 4;            // 0..127
        const int c4  = idx & 15;
        Bf[it] = *(const float4*)(Bg + (size_t)row * HH + kc * BK + c4 * 4);
    }
}

__device__ __forceinline__ void sts_B(char* stage, int tid, const float4* Bf) {
    #pragma unroll
    for (int it = 0; it < 8; it++) {
        const int idx = tid + it * THREADS;
        const int row = idx >> 4;
        const int c4  = idx & 15;
        __half2 h0; h0.x = __float2half(Bf[it].x); h0.y = __float2half(Bf[it].y);
        __half2 h1; h1.x = __float2half(Bf[it].z); h1.y = __float2half(Bf[it].w);
        uint2 v;
        v.x = *(uint32_t*)&h0;
        v.y = *(uint32_t*)&h1;
        const uint32_t off = SWZ((uint32_t)(row * 128 + c4 * 8));
        *(uint2*)(stage + OFF_B + off) = v;
    }
}

// ---------------------------------------------------------------------------
// GEMM: CTA tile 128x128, nchunk K-chunks of 64. 8 warps, warp tile m64 x n32.
// sts_B for chunk k+1 is buried mid-MMA-loop (after k16==2) to hide its issue
// cost and LDG latency inside the tensor shadow.
// ---------------------------------------------------------------------------
__device__ __forceinline__ void gemm_body(const __half* Ag,
                                          const float* Bg, const float* bias,
                                          float* C, int ldc, int nchunk) {
    extern __shared__ char smem[];
    const uint32_t sbase = smem_to_u32(smem);
    const int tid  = threadIdx.x;
    const int lane = tid & 31;
    const int wid  = tid >> 5;
    const int wm   = wid & 1;          // m64 block (0..1)
    const int wn   = wid >> 1;         // n32 block (0..3)

    float acc[4][4][4];
    #pragma unroll
    for (int mt = 0; mt < 4; mt++)
        #pragma unroll
        for (int nt = 0; nt < 4; nt++)
            #pragma unroll
            for (int i = 0; i < 4; i++) acc[mt][nt][i] = 0.0f;

    const int a_row = (lane & 15);
    const int a_kb  = (lane >> 4) * 16;
    const int b_row = (lane & 7) + ((lane >> 4) << 3);
    const int b_kb  = ((lane >> 3) & 1) * 16;

    float4 Bf[8];

    ldg_B(Bg, 0, tid, Bf);
    cpasync_A(Ag, sbase, 0, tid);
    CP_COMMIT();
    sts_B(smem, tid, Bf);
    CP_WAIT0();
    __syncthreads();

    for (int kc = 0; kc < nchunk; kc++) {
        const int st = kc & 1;
        const uint32_t sb = sbase + st * STAGE;
        char* alt = smem + (st ^ 1) * STAGE;
        const bool has_next = (kc + 1 < nchunk);

        if (has_next) {
            ldg_B(Bg, kc + 1, tid, Bf);
            cpasync_A(Ag, sbase + (st ^ 1) * STAGE, kc + 1, tid);
            CP_COMMIT();
        }

        #pragma unroll
        for (int k16 = 0; k16 < 4; k16++) {
            const int kb = k16 * 32;
            uint32_t ah[4][4];
            #pragma unroll
            for (int mt = 0; mt < 4; mt++) {
                const uint32_t off = SWZ((uint32_t)((wm * 64 + mt * 16 + a_row) * 128 + kb + a_kb));
                ldsm4(ah[mt], sb + off);
            }
            uint32_t bh[4][2];
            #pragma unroll
            for (int nq = 0; nq < 2; nq++) {
                const uint32_t off = SWZ((uint32_t)((wn * 32 + nq * 16 + b_row) * 128 + kb + b_kb));
                uint32_t r[4];
                ldsm4(r, sb + OFF_B + off);
                bh[nq * 2][0] = r[0]; bh[nq * 2][1] = r[1];
                bh[nq * 2 + 1][0] = r[2]; bh[nq * 2 + 1][1] = r[3];
            }
            #pragma unroll
            for (int mt = 0; mt < 4; mt++)
                #pragma unroll
                for (int nt = 0; nt < 4; nt++)
                    mma16816(acc[mt][nt], ah[mt], bh[nt]);

            // Bury next chunk's B convert+store in the MMA shadow (~3/4 through,
            // LDG data has landed even from DRAM by now).
            if (k16 == 2 && has_next)
                sts_B(alt, tid, Bf);
        }

        if (has_next) CP_WAIT0();
        __syncthreads();
    }

    const int erow = (lane >> 2);
    const int ecol = (lane & 3) * 2;
    #pragma unroll
    for (int mt = 0; mt < 4; mt++) {
        #pragma unroll
        for (int nt = 0; nt < 4; nt++) {
            const int r0 = wm * 64 + mt * 16 + erow;
            const int cc = wn * 32 + nt * 8 + ecol;
            float b0 = 0.f, b1 = 0.f;
            if (bias) { b0 = bias[cc]; b1 = bias[cc + 1]; }
            float2 v0 = make_float2(acc[mt][nt][0] + b0, acc[mt][nt][1] + b1);
            float2 v1 = make_float2(acc[mt][nt][2] + b0, acc[mt][nt][3] + b1);
            *(float2*)(C + (size_t)r0 * ldc + cc)       = v0;
            *(float2*)(C + (size_t)(r0 + 8) * ldc + cc) = v1;
        }
    }
}

// ---------------------------------------------------------------------------
// Global wrappers
// ---------------------------------------------------------------------------
// Recurrent: split-K(4). grid = (32 ntiles, 2 mtiles, 4 kh) = 256 CTAs.
__global__ void __launch_bounds__(THREADS, 2) gemm_rec_tc(const float* __restrict__ Wh, int t) {
    const int ntile = blockIdx.x;
    const int mtile = blockIdx.y;
    const int kh    = blockIdx.z;
    gemm_body(&g_hh[t - 1][mtile * 128][kh * 256],
              Wh + (size_t)t * G4 * HH + (size_t)ntile * 128 * HH + kh * 256,
              nullptr,
              &g_acc[kh][mtile * 128][ntile * 128], G4, 4);
}

__global__ void __launch_bounds__(THREADS, 2) gemm_log_tc(const float* __restrict__ Wout,
                                                          const float* __restrict__ bout,
                                                          float* __restrict__ out, int t) {
    const int mtile = blockIdx.x & 1;            // adjacent CTAs share Wout tile via L2
    const int ntile = blockIdx.x >> 1;           // 0..249
    gemm_body(&g_hh[t][mtile * 128][0],
              Wout + (size_t)t * VV * HH + (size_t)ntile * 128 * HH,
              bout + (size_t)t * VV + ntile * 128,
              out + (size_t)mtile * 128 * TT * VV + (size_t)t * VV + ntile * 128,
              TT * VV, 16);
}

// ---------------------------------------------------------------------------
// Gates / cell update (sums 4 split-K partials, emits fp16 h)
// ---------------------------------------------------------------------------
__device__ __forceinline__ float sigf(float v) { return 1.0f / (1.0f + expf(-v)); }

__global__ void gates_kernel(const float* __restrict__ x,
                             const float* __restrict__ Wx,
                             const float* __restrict__ bh,
                             int t, int first) {
    const int idx = blockIdx.x * blockDim.x + threadIdx.x;
    const int b = idx >> 10;
    const int hh = idx & (HH - 1);

    const float xb = x[b * TT + t];
    const float* wx  = Wx + (size_t)t * 4 * HH;
    const float* bht = bh + (size_t)t * 4 * HH;

    float p[4];
    #pragma unroll
    for (int g = 0; g < 4; g++) {
        float v = xb * wx[g * HH + hh];
        if (!first) {
            v += g_acc[0][b][g * HH + hh] + g_acc[1][b][g * HH + hh]
               + g_acc[2][b][g * HH + hh] + g_acc[3][b][g * HH + hh]
               + bht[g * HH + hh];
        }
        p[g] = v;
    }
    const float f_ = sigf(p[0]);
    const float i_ = sigf(p[1]);
    const float cb = tanhf(p[2]);
    const float o_ = sigf(p[3]);

    float c = first ? (i_ * cb) : fmaf(f_, g_c[b][hh], i_ * cb);
    g_c[b][hh] = c;
    const float hv = o_ * tanhf(c);
    g_hh[t][b][hh] = __float2half(hv);
}

// ---------------------------------------------------------------------------
// Entry point (single stream)
// ---------------------------------------------------------------------------
extern "C" void kernel_launch(void* const* d_in, const int* in_sizes, int n_in,
                              void* d_out, int out_size) {
    const float* x    = (const float*)d_in[0];
    const float* Wx   = (const float*)d_in[1];
    const float* Wh   = (const float*)d_in[2];
    const float* bh   = (const float*)d_in[3];
    const float* Wout = (const float*)d_in[4];
    const float* bout = (const float*)d_in[5];
    float* out = (float*)d_out;

    cudaFuncSetAttribute(gemm_rec_tc, cudaFuncAttributeMaxDynamicSharedMemorySize, SMEM_GEMM);
    cudaFuncSetAttribute(gemm_log_tc, cudaFuncAttributeMaxDynamicSharedMemorySize, SMEM_GEMM);

    const int gate_blocks = (BB * HH) / 256;

    gates_kernel<<<gate_blocks, 256>>>(x, Wx, bh, 0, 1);
    for (int t = 1; t < TT; t++) {
        gemm_rec_tc<<<dim3(32, 2, 4), THREADS, SMEM_GEMM>>>(Wh, t);  // 256 CTAs
        gates_kernel<<<gate_blocks, 256>>>(x, Wx, bh, t, 0);
    }
    for (int t = 0; t < TT; t++)
        gemm_log_tc<<<500, THREADS, SMEM_GEMM>>>(Wout, bout, out, t);
}

// round 15
// speedup vs baseline: 1.2284x; 1.2284x over previous
#include <cuda_runtime.h>
#include <cuda_fp16.h>
#include <math.h>
#include <stdint.h>

#define BB 256
#define TT 8
#define HH 1024
#define VV 32000
#define G4 4096

#define BK 64              // k elems per chunk (64 fp16 = 128 B row)
#define THREADS 256        // 8 warps: wm = wid&1 (m64), wn = wid>>1 (n32)

// CTA tile 128x128. Stage: [A 16K][B 16K]
#define OFF_B  16384
#define STAGE  32768
#define SMEM_GEMM (2 * STAGE)   // 65536 per CTA; 2 CTAs/SM
#define SWZ(off) ((off) ^ (((off) >> 3) & 0x70))

// ---------------------------------------------------------------------------
// scratch (device globals only)
// ---------------------------------------------------------------------------
__device__ __half g_hh[TT][BB][HH];    // h in fp16 (A operand)
__device__ float g_c[BB][HH];
__device__ float g_acc[4][BB][G4];     // split-K(4) partials for recurrent GEMM

// ---------------------------------------------------------------------------
// PTX helpers (sm_80-level only)
// ---------------------------------------------------------------------------
__device__ __forceinline__ uint32_t smem_to_u32(const void* p) {
    uint32_t a;
    asm("{ .reg .u64 t; cvta.to.shared.u64 t, %1; cvt.u32.u64 %0, t; }" : "=r"(a) : "l"(p));
    return a;
}
__device__ __forceinline__ void ldsm4(uint32_t* r, uint32_t addr) {
    asm volatile("ldmatrix.sync.aligned.m8n8.x4.shared.b16 {%0,%1,%2,%3}, [%4];"
                 : "=r"(r[0]), "=r"(r[1]), "=r"(r[2]), "=r"(r[3]) : "r"(addr));
}
__device__ __forceinline__ void mma16816(float* c, const uint32_t* a, const uint32_t* b) {
    asm volatile(
        "mma.sync.aligned.m16n8k16.row.col.f32.f16.f16.f32 "
        "{%0,%1,%2,%3}, {%4,%5,%6,%7}, {%8,%9}, {%0,%1,%2,%3};"
        : "+f"(c[0]), "+f"(c[1]), "+f"(c[2]), "+f"(c[3])
        : "r"(a[0]), "r"(a[1]), "r"(a[2]), "r"(a[3]), "r"(b[0]), "r"(b[1]));
}
__device__ __forceinline__ void cp16(uint32_t dst, const void* src) {
    asm volatile("cp.async.cg.shared.global [%0], [%1], 16;" :: "r"(dst), "l"(src));
}
#define CP_COMMIT() asm volatile("cp.async.commit_group;" ::: "memory")
#define CP_WAIT0()  asm volatile("cp.async.wait_group 0;" ::: "memory")

// ---------------------------------------------------------------------------
// Loaders (256 threads, CTA 128x128)
// ---------------------------------------------------------------------------
__device__ __forceinline__ void cpasync_A(const __half* __restrict__ Ag,
                                          uint32_t stage_u32, int kc, int tid) {
    #pragma unroll
    for (int u = 0; u < 4; u++) {
        const int idx = tid + u * THREADS;   // 0..1023
        const int row = idx >> 3;            // 0..127
        const int j   = idx & 7;
        const uint32_t off = SWZ((uint32_t)(row * 128 + j * 16));
        cp16(stage_u32 + off, Ag + (size_t)row * HH + kc * BK + j * 8);
    }
}

__device__ __forceinline__ void ldg_B(const float* __restrict__ Bg, int kc, int tid,
                                      float4* Bf) {
    #pragma unroll
    for (int it = 0; it < 8; it++) {
        const int idx = tid + it * THREADS;  // 0..2047
        const int row = idx >> 4;            // 0..127
        const int c4  = idx & 15;
        Bf[it] = *(const float4*)(Bg + (size_t)row * HH + kc * BK + c4 * 4);
    }
}

__device__ __forceinline__ void sts_B(char* stage, int tid, const float4* Bf) {
    #pragma unroll
    for (int it = 0; it < 8; it++) {
        const int idx = tid + it * THREADS;
        const int row = idx >> 4;
        const int c4  = idx & 15;
        __half2 h0; h0.x = __float2half(Bf[it].x); h0.y = __float2half(Bf[it].y);
        __half2 h1; h1.x = __float2half(Bf[it].z); h1.y = __float2half(Bf[it].w);
        uint2 v;
        v.x = *(uint32_t*)&h0;
        v.y = *(uint32_t*)&h1;
        const uint32_t off = SWZ((uint32_t)(row * 128 + c4 * 8));
        *(uint2*)(stage + OFF_B + off) = v;
    }
}

// ---------------------------------------------------------------------------
// GEMM: CTA tile 128x128, nchunk K-chunks of 64. 8 warps, warp tile m64 x n32.
// (R11 inner-loop structure: sts_B in the chunk tail.)
// ---------------------------------------------------------------------------
__device__ __forceinline__ void gemm_body(const __half* Ag,
                                          const float* Bg, const float* bias,
                                          float* C, int ldc, int nchunk) {
    extern __shared__ char smem[];
    const uint32_t sbase = smem_to_u32(smem);
    const int tid  = threadIdx.x;
    const int lane = tid & 31;
    const int wid  = tid >> 5;
    const int wm   = wid & 1;          // m64 block (0..1)
    const int wn   = wid >> 1;         // n32 block (0..3)

    float acc[4][4][4];
    #pragma unroll
    for (int mt = 0; mt < 4; mt++)
        #pragma unroll
        for (int nt = 0; nt < 4; nt++)
            #pragma unroll
            for (int i = 0; i < 4; i++) acc[mt][nt][i] = 0.0f;

    const int a_row = (lane & 15);
    const int a_kb  = (lane >> 4) * 16;
    const int b_row = (lane & 7) + ((lane >> 4) << 3);
    const int b_kb  = ((lane >> 3) & 1) * 16;

    float4 Bf[8];

    ldg_B(Bg, 0, tid, Bf);
    cpasync_A(Ag, sbase, 0, tid);
    CP_COMMIT();
    sts_B(smem, tid, Bf);
    CP_WAIT0();
    __syncthreads();

    for (int kc = 0; kc < nchunk; kc++) {
        const int st = kc & 1;
        const uint32_t sb = sbase + st * STAGE;
        char* alt = smem + (st ^ 1) * STAGE;

        if (kc + 1 < nchunk) {
            ldg_B(Bg, kc + 1, tid, Bf);
            cpasync_A(Ag, sbase + (st ^ 1) * STAGE, kc + 1, tid);
            CP_COMMIT();
        }

        #pragma unroll
        for (int k16 = 0; k16 < 4; k16++) {
            const int kb = k16 * 32;
            uint32_t ah[4][4];
            #pragma unroll
            for (int mt = 0; mt < 4; mt++) {
                const uint32_t off = SWZ((uint32_t)((wm * 64 + mt * 16 + a_row) * 128 + kb + a_kb));
                ldsm4(ah[mt], sb + off);
            }
            uint32_t bh[4][2];
            #pragma unroll
            for (int nq = 0; nq < 2; nq++) {
                const uint32_t off = SWZ((uint32_t)((wn * 32 + nq * 16 + b_row) * 128 + kb + b_kb));
                uint32_t r[4];
                ldsm4(r, sb + OFF_B + off);
                bh[nq * 2][0] = r[0]; bh[nq * 2][1] = r[1];
                bh[nq * 2 + 1][0] = r[2]; bh[nq * 2 + 1][1] = r[3];
            }
            #pragma unroll
            for (int mt = 0; mt < 4; mt++)
                #pragma unroll
                for (int nt = 0; nt < 4; nt++)
                    mma16816(acc[mt][nt], ah[mt], bh[nt]);
        }

        if (kc + 1 < nchunk) {
            sts_B(alt, tid, Bf);
            CP_WAIT0();
        }
        __syncthreads();
    }

    const int erow = (lane >> 2);
    const int ecol = (lane & 3) * 2;
    #pragma unroll
    for (int mt = 0; mt < 4; mt++) {
        #pragma unroll
        for (int nt = 0; nt < 4; nt++) {
            const int r0 = wm * 64 + mt * 16 + erow;
            const int cc = wn * 32 + nt * 8 + ecol;
            float b0 = 0.f, b1 = 0.f;
            if (bias) { b0 = bias[cc]; b1 = bias[cc + 1]; }
            float2 v0 = make_float2(acc[mt][nt][0] + b0, acc[mt][nt][1] + b1);
            float2 v1 = make_float2(acc[mt][nt][2] + b0, acc[mt][nt][3] + b1);
            *(float2*)(C + (size_t)r0 * ldc + cc)       = v0;
            *(float2*)(C + (size_t)(r0 + 8) * ldc + cc) = v1;
        }
    }
}

// ---------------------------------------------------------------------------
// Global wrappers
// ---------------------------------------------------------------------------
// Recurrent: split-K(4). grid = (32 ntiles, 2 mtiles, 4 kh) = 256 CTAs.
__global__ void __launch_bounds__(THREADS, 2) gemm_rec_tc(const float* __restrict__ Wh, int t) {
    const int ntile = blockIdx.x;
    const int mtile = blockIdx.y;
    const int kh    = blockIdx.z;
    gemm_body(&g_hh[t - 1][mtile * 128][kh * 256],
              Wh + (size_t)t * G4 * HH + (size_t)ntile * 128 * HH + kh * 256,
              nullptr,
              &g_acc[kh][mtile * 128][ntile * 128], G4, 4);
}

// Logits: ONE launch, grid (500, 1, TT). Adjacent CTAs share a Wout tile (L2).
__global__ void __launch_bounds__(THREADS, 2) gemm_log_tc(const float* __restrict__ Wout,
                                                          const float* __restrict__ bout,
                                                          float* __restrict__ out) {
    const int t = blockIdx.z;
    const int mtile = blockIdx.x & 1;
    const int ntile = blockIdx.x >> 1;           // 0..249
    gemm_body(&g_hh[t][mtile * 128][0],
              Wout + (size_t)t * VV * HH + (size_t)ntile * 128 * HH,
              bout + (size_t)t * VV + ntile * 128,
              out + (size_t)mtile * 128 * TT * VV + (size_t)t * VV + ntile * 128,
              TT * VV, 16);
}

// ---------------------------------------------------------------------------
// Gates / cell update (sums 4 split-K partials, emits fp16 h)
// ---------------------------------------------------------------------------
__device__ __forceinline__ float sigf(float v) { return 1.0f / (1.0f + expf(-v)); }

__global__ void gates_kernel(const float* __restrict__ x,
                             const float* __restrict__ Wx,
                             const float* __restrict__ bh,
                             int t, int first) {
    const int idx = blockIdx.x * blockDim.x + threadIdx.x;
    const int b = idx >> 10;
    const int hh = idx & (HH - 1);

    const float xb = x[b * TT + t];
    const float* wx  = Wx + (size_t)t * 4 * HH;
    const float* bht = bh + (size_t)t * 4 * HH;

    float p[4];
    #pragma unroll
    for (int g = 0; g < 4; g++) {
        float v = xb * wx[g * HH + hh];
        if (!first) {
            v += g_acc[0][b][g * HH + hh] + g_acc[1][b][g * HH + hh]
               + g_acc[2][b][g * HH + hh] + g_acc[3][b][g * HH + hh]
               + bht[g * HH + hh];
        }
        p[g] = v;
    }
    const float f_ = sigf(p[0]);
    const float i_ = sigf(p[1]);
    const float cb = tanhf(p[2]);
    const float o_ = sigf(p[3]);

    float c = first ? (i_ * cb) : fmaf(f_, g_c[b][hh], i_ * cb);
    g_c[b][hh] = c;
    const float hv = o_ * tanhf(c);
    g_hh[t][b][hh] = __float2half(hv);
}

// ---------------------------------------------------------------------------
// Entry point (single stream)
// ---------------------------------------------------------------------------
extern "C" void kernel_launch(void* const* d_in, const int* in_sizes, int n_in,
                              void* d_out, int out_size) {
    const float* x    = (const float*)d_in[0];
    const float* Wx   = (const float*)d_in[1];
    const float* Wh   = (const float*)d_in[2];
    const float* bh   = (const float*)d_in[3];
    const float* Wout = (const float*)d_in[4];
    const float* bout = (const float*)d_in[5];
    float* out = (float*)d_out;

    cudaFuncSetAttribute(gemm_rec_tc, cudaFuncAttributeMaxDynamicSharedMemorySize, SMEM_GEMM);
    cudaFuncSetAttribute(gemm_log_tc, cudaFuncAttributeMaxDynamicSharedMemorySize, SMEM_GEMM);

    const int gate_blocks = (BB * HH) / 256;

    gates_kernel<<<gate_blocks, 256>>>(x, Wx, bh, 0, 1);
    for (int t = 1; t < TT; t++) {
        gemm_rec_tc<<<dim3(32, 2, 4), THREADS, SMEM_GEMM>>>(Wh, t);  // 256 CTAs
        gates_kernel<<<gate_blocks, 256>>>(x, Wx, bh, t, 0);
    }
    gemm_log_tc<<<dim3(500, 1, TT), THREADS, SMEM_GEMM>>>(Wout, bout, out);
}

// round 16
// speedup vs baseline: 1.3596x; 1.1068x over previous
#include <cuda_runtime.h>
#include <cuda_fp16.h>
#include <math.h>
#include <stdint.h>

#define BB 256
#define TT 8
#define HH 1024
#define VV 32000
#define G4 4096

#define BK 64              // k elems per chunk (64 fp16 = 128 B row)
#define THREADS 256        // 8 warps: wm = wid&1 (m64), wn = wid>>1 (n32)

// CTA tile 128x128. Stage: [A 16K][B 16K]
#define OFF_B  16384
#define STAGE  32768
#define SMEM_GEMM (2 * STAGE)   // 65536 per CTA; 2 CTAs/SM
#define SWZ(off) ((off) ^ (((off) >> 3) & 0x70))

// ---------------------------------------------------------------------------
// scratch (device globals only)
// ---------------------------------------------------------------------------
__device__ __half g_hh[TT][BB][HH];    // h in fp16 (A operand)
__device__ float g_c[BB][HH];
__device__ float g_acc[2][BB][G4];     // split-K(2) partials for recurrent GEMM

// ---------------------------------------------------------------------------
// PTX helpers (sm_80-level only)
// ---------------------------------------------------------------------------
__device__ __forceinline__ uint32_t smem_to_u32(const void* p) {
    uint32_t a;
    asm("{ .reg .u64 t; cvta.to.shared.u64 t, %1; cvt.u32.u64 %0, t; }" : "=r"(a) : "l"(p));
    return a;
}
__device__ __forceinline__ void ldsm4(uint32_t* r, uint32_t addr) {
    asm volatile("ldmatrix.sync.aligned.m8n8.x4.shared.b16 {%0,%1,%2,%3}, [%4];"
                 : "=r"(r[0]), "=r"(r[1]), "=r"(r[2]), "=r"(r[3]) : "r"(addr));
}
__device__ __forceinline__ void mma16816(float* c, const uint32_t* a, const uint32_t* b) {
    asm volatile(
        "mma.sync.aligned.m16n8k16.row.col.f32.f16.f16.f32 "
        "{%0,%1,%2,%3}, {%4,%5,%6,%7}, {%8,%9}, {%0,%1,%2,%3};"
        : "+f"(c[0]), "+f"(c[1]), "+f"(c[2]), "+f"(c[3])
        : "r"(a[0]), "r"(a[1]), "r"(a[2]), "r"(a[3]), "r"(b[0]), "r"(b[1]));
}
__device__ __forceinline__ void cp16(uint32_t dst, const void* src) {
    asm volatile("cp.async.cg.shared.global [%0], [%1], 16;" :: "r"(dst), "l"(src));
}
#define CP_COMMIT() asm volatile("cp.async.commit_group;" ::: "memory")
#define CP_WAIT0()  asm volatile("cp.async.wait_group 0;" ::: "memory")

// ---------------------------------------------------------------------------
// Loaders (256 threads, CTA 128x128)
// ---------------------------------------------------------------------------
__device__ __forceinline__ void cpasync_A(const __half* __restrict__ Ag,
                                          uint32_t stage_u32, int kc, int tid) {
    #pragma unroll
    for (int u = 0; u < 4; u++) {
        const int idx = tid + u * THREADS;   // 0..1023
        const int row = idx >> 3;            // 0..127
        const int j   = idx & 7;
        const uint32_t off = SWZ((uint32_t)(row * 128 + j * 16));
        cp16(stage_u32 + off, Ag + (size_t)row * HH + kc * BK + j * 8);
    }
}

__device__ __forceinline__ void ldg_B(const float* __restrict__ Bg, int kc, int tid,
                                      float4* Bf) {
    #pragma unroll
    for (int it = 0; it < 8; it++) {
        const int idx = tid + it * THREADS;  // 0..2047
        const int row = idx >> 4;            // 0..127
        const int c4  = idx & 15;
        Bf[it] = *(const float4*)(Bg + (size_t)row * HH + kc * BK + c4 * 4);
    }
}

__device__ __forceinline__ void sts_B(char* stage, int tid, const float4* Bf) {
    #pragma unroll
    for (int it = 0; it < 8; it++) {
        const int idx = tid + it * THREADS;
        const int row = idx >> 4;
        const int c4  = idx & 15;
        __half2 h0; h0.x = __float2half(Bf[it].x); h0.y = __float2half(Bf[it].y);
        __half2 h1; h1.x = __float2half(Bf[it].z); h1.y = __float2half(Bf[it].w);
        uint2 v;
        v.x = *(uint32_t*)&h0;
        v.y = *(uint32_t*)&h1;
        const uint32_t off = SWZ((uint32_t)(row * 128 + c4 * 8));
        *(uint2*)(stage + OFF_B + off) = v;
    }
}

// ---------------------------------------------------------------------------
// GEMM: CTA tile 128x128, nchunk K-chunks of 64. 8 warps, warp tile m64 x n32.
// ---------------------------------------------------------------------------
__device__ __forceinline__ void gemm_body(const __half* Ag,
                                          const float* Bg, const float* bias,
                                          float* C, int ldc, int nchunk) {
    extern __shared__ char smem[];
    const uint32_t sbase = smem_to_u32(smem);
    const int tid  = threadIdx.x;
    const int lane = tid & 31;
    const int wid  = tid >> 5;
    const int wm   = wid & 1;          // m64 block (0..1)
    const int wn   = wid >> 1;         // n32 block (0..3)

    float acc[4][4][4];
    #pragma unroll
    for (int mt = 0; mt < 4; mt++)
        #pragma unroll
        for (int nt = 0; nt < 4; nt++)
            #pragma unroll
            for (int i = 0; i < 4; i++) acc[mt][nt][i] = 0.0f;

    const int a_row = (lane & 15);
    const int a_kb  = (lane >> 4) * 16;
    const int b_row = (lane & 7) + ((lane >> 4) << 3);
    const int b_kb  = ((lane >> 3) & 1) * 16;

    float4 Bf[8];

    ldg_B(Bg, 0, tid, Bf);
    cpasync_A(Ag, sbase, 0, tid);
    CP_COMMIT();
    sts_B(smem, tid, Bf);
    CP_WAIT0();
    __syncthreads();

    for (int kc = 0; kc < nchunk; kc++) {
        const int st = kc & 1;
        const uint32_t sb = sbase + st * STAGE;
        char* alt = smem + (st ^ 1) * STAGE;

        if (kc + 1 < nchunk) {
            ldg_B(Bg, kc + 1, tid, Bf);
            cpasync_A(Ag, sbase + (st ^ 1) * STAGE, kc + 1, tid);
            CP_COMMIT();
        }

        #pragma unroll
        for (int k16 = 0; k16 < 4; k16++) {
            const int kb = k16 * 32;
            uint32_t ah[4][4];
            #pragma unroll
            for (int mt = 0; mt < 4; mt++) {
                const uint32_t off = SWZ((uint32_t)((wm * 64 + mt * 16 + a_row) * 128 + kb + a_kb));
                ldsm4(ah[mt], sb + off);
            }
            uint32_t bh[4][2];
            #pragma unroll
            for (int nq = 0; nq < 2; nq++) {
                const uint32_t off = SWZ((uint32_t)((wn * 32 + nq * 16 + b_row) * 128 + kb + b_kb));
                uint32_t r[4];
                ldsm4(r, sb + OFF_B + off);
                bh[nq * 2][0] = r[0]; bh[nq * 2][1] = r[1];
                bh[nq * 2 + 1][0] = r[2]; bh[nq * 2 + 1][1] = r[3];
            }
            #pragma unroll
            for (int mt = 0; mt < 4; mt++)
                #pragma unroll
                for (int nt = 0; nt < 4; nt++)
                    mma16816(acc[mt][nt], ah[mt], bh[nt]);
        }

        if (kc + 1 < nchunk) {
            sts_B(alt, tid, Bf);
            CP_WAIT0();
        }
        __syncthreads();
    }

    const int erow = (lane >> 2);
    const int ecol = (lane & 3) * 2;
    #pragma unroll
    for (int mt = 0; mt < 4; mt++) {
        #pragma unroll
        for (int nt = 0; nt < 4; nt++) {
            const int r0 = wm * 64 + mt * 16 + erow;
            const int cc = wn * 32 + nt * 8 + ecol;
            float b0 = 0.f, b1 = 0.f;
            if (bias) { b0 = bias[cc]; b1 = bias[cc + 1]; }
            float2 v0 = make_float2(acc[mt][nt][0] + b0, acc[mt][nt][1] + b1);
            float2 v1 = make_float2(acc[mt][nt][2] + b0, acc[mt][nt][3] + b1);
            *(float2*)(C + (size_t)r0 * ldc + cc)       = v0;
            *(float2*)(C + (size_t)(r0 + 8) * ldc + cc) = v1;
        }
    }
}

// ---------------------------------------------------------------------------
// Global wrappers
// ---------------------------------------------------------------------------
// Recurrent: split-K(2). grid = (32 ntiles, 2 mtiles, 2 kh) = 128 CTAs.
__global__ void __launch_bounds__(THREADS, 2) gemm_rec_tc(const float* __restrict__ Wh, int t) {
    const int ntile = blockIdx.x;
    const int mtile = blockIdx.y;
    const int kh    = blockIdx.z;
    gemm_body(&g_hh[t - 1][mtile * 128][kh * 512],
              Wh + (size_t)t * G4 * HH + (size_t)ntile * 128 * HH + kh * 512,
              nullptr,
              &g_acc[kh][mtile * 128][ntile * 128], G4, 8);
}

// Logits for one timestep: 500 CTAs, mtile-adjacent pairs share Wout via L2.
__global__ void __launch_bounds__(THREADS, 2) gemm_log_tc(const float* __restrict__ Wout,
                                                          const float* __restrict__ bout,
                                                          float* __restrict__ out, int t) {
    const int mtile = blockIdx.x & 1;
    const int ntile = blockIdx.x >> 1;           // 0..249
    gemm_body(&g_hh[t][mtile * 128][0],
              Wout + (size_t)t * VV * HH + (size_t)ntile * 128 * HH,
              bout + (size_t)t * VV + ntile * 128,
              out + (size_t)mtile * 128 * TT * VV + (size_t)t * VV + ntile * 128,
              TT * VV, 16);
}

// ---------------------------------------------------------------------------
// Gates / cell update (sums split-K partials, emits fp16 h)
// ---------------------------------------------------------------------------
__device__ __forceinline__ float sigf(float v) { return 1.0f / (1.0f + expf(-v)); }

__global__ void gates_kernel(const float* __restrict__ x,
                             const float* __restrict__ Wx,
                             const float* __restrict__ bh,
                             int t, int first) {
    const int idx = blockIdx.x * blockDim.x + threadIdx.x;
    const int b = idx >> 10;
    const int hh = idx & (HH - 1);

    const float xb = x[b * TT + t];
    const float* wx  = Wx + (size_t)t * 4 * HH;
    const float* bht = bh + (size_t)t * 4 * HH;

    float p[4];
    #pragma unroll
    for (int g = 0; g < 4; g++) {
        float v = xb * wx[g * HH + hh];
        if (!first) {
            v += g_acc[0][b][g * HH + hh] + g_acc[1][b][g * HH + hh]
               + bht[g * HH + hh];
        }
        p[g] = v;
    }
    const float f_ = sigf(p[0]);
    const float i_ = sigf(p[1]);
    const float cb = tanhf(p[2]);
    const float o_ = sigf(p[3]);

    float c = first ? (i_ * cb) : fmaf(f_, g_c[b][hh], i_ * cb);
    g_c[b][hh] = c;
    const float hv = o_ * tanhf(c);
    g_hh[t][b][hh] = __float2half(hv);
}

// ---------------------------------------------------------------------------
// Entry point — overlap DAG with the R13 tail-wave confound removed:
//   s_hi (high prio): gates0 -> rec1 -> gates1 -> ... -> gates7
//   s_a / s_b (low prio, alternating): logits(t) waits only on ev_g[t];
//   launches on different streams overlap each other's tail waves.
// ---------------------------------------------------------------------------
extern "C" void kernel_launch(void* const* d_in, const int* in_sizes, int n_in,
                              void* d_out, int out_size) {
    const float* x    = (const float*)d_in[0];
    const float* Wx   = (const float*)d_in[1];
    const float* Wh   = (const float*)d_in[2];
    const float* bh   = (const float*)d_in[3];
    const float* Wout = (const float*)d_in[4];
    const float* bout = (const float*)d_in[5];
    float* out = (float*)d_out;

    static cudaStream_t s_hi = nullptr, s_a = nullptr, s_b = nullptr;
    static cudaEvent_t ev_root = nullptr, ev_g[TT], ev_a = nullptr, ev_b = nullptr;
    if (s_hi == nullptr) {
        int prio_lo, prio_hi;
        cudaDeviceGetStreamPriorityRange(&prio_lo, &prio_hi);
        cudaStreamCreateWithPriority(&s_hi, cudaStreamNonBlocking, prio_hi);
        cudaStreamCreateWithPriority(&s_a,  cudaStreamNonBlocking, prio_lo);
        cudaStreamCreateWithPriority(&s_b,  cudaStreamNonBlocking, prio_lo);
        cudaEventCreateWithFlags(&ev_root, cudaEventDisableTiming);
        cudaEventCreateWithFlags(&ev_a, cudaEventDisableTiming);
        cudaEventCreateWithFlags(&ev_b, cudaEventDisableTiming);
        for (int t = 0; t < TT; t++)
            cudaEventCreateWithFlags(&ev_g[t], cudaEventDisableTiming);
        cudaFuncSetAttribute(gemm_rec_tc, cudaFuncAttributeMaxDynamicSharedMemorySize, SMEM_GEMM);
        cudaFuncSetAttribute(gemm_log_tc, cudaFuncAttributeMaxDynamicSharedMemorySize, SMEM_GEMM);
    }

    const int gate_blocks = (BB * HH) / 256;

    // Fork worker streams off the (captured) legacy stream.
    cudaEventRecord(ev_root, 0);
    cudaStreamWaitEvent(s_hi, ev_root, 0);
    cudaStreamWaitEvent(s_a,  ev_root, 0);
    cudaStreamWaitEvent(s_b,  ev_root, 0);

    // Serial recurrence chain on the high-priority stream.
    gates_kernel<<<gate_blocks, 256, 0, s_hi>>>(x, Wx, bh, 0, 1);
    cudaEventRecord(ev_g[0], s_hi);
    for (int t = 1; t < TT; t++) {
        gemm_rec_tc<<<dim3(32, 2, 2), THREADS, SMEM_GEMM, s_hi>>>(Wh, t);
        gates_kernel<<<gate_blocks, 256, 0, s_hi>>>(x, Wx, bh, t, 0);
        cudaEventRecord(ev_g[t], s_hi);
    }

    // Logits on two alternating low-priority streams: tails overlap.
    for (int t = 0; t < TT; t++) {
        cudaStream_t s = (t & 1) ? s_b : s_a;
        cudaStreamWaitEvent(s, ev_g[t], 0);
        gemm_log_tc<<<500, THREADS, SMEM_GEMM, s>>>(Wout, bout, out, t);
    }
    cudaEventRecord(ev_a, s_a);
    cudaEventRecord(ev_b, s_b);

    // Join back to the legacy stream (chain joins transitively via ev_g[7]).
    cudaStreamWaitEvent(0, ev_a, 0);
    cudaStreamWaitEvent(0, ev_b, 0);
}